// round 8
// baseline (speedup 1.0000x reference)
#include <cuda_runtime.h>
#include <cuda_fp16.h>
#include <cstdint>

#define T_STEPS 2048
#define BATCH   128
#define DIM     100
#define HID     1024
#define NBLK    64
#define JT      16          // H columns per block
#define NTH     512         // 16 warps: 8 row-bands x 2 col-halves
#define KC      128         // k-halfs per chunk
#define XW      128         // padded x width (100 -> 128)
#define NSLOT   5           // 4 rotating h slots + 1 x slot (per band)
#define SLOT_X  4
#define APITCH_B 272        // bytes per A row (128 halfs + 8 pad); ldsm conflict-free
#define AW_B    (16*APITCH_B)                 // 4352 B: one slot (16 rows)
#define WPITCH_H 1160       // halfs per W row (1152 + 8 pad)
#define WPITCH_B 2320
#define SMEM_W_OFF   (8*NSLOT*AW_B)           // 174080
#define SMEM_BIAS_OFF (SMEM_W_OFF + JT*WPITCH_B)  // 211200
#define SMEM_TOTAL   (SMEM_BIAS_OFF + 64)

// ---------------- device scratch ----------------
__device__ __half g_xT[(size_t)(T_STEPS + 1) * BATCH * XW]; // +1 zero-padded step
__device__ __half g_h[3][BATCH * HID];                 // triple-buffered hidden state
__device__ float  g_hlast[BATCH * HID];
__device__ unsigned g_cnt[8 * 32];                     // [band][group]: band*32+g
__device__ unsigned g_bar_count;
__device__ unsigned g_bar_gen;

// ---------------- PTX helpers ----------------
__device__ __forceinline__ void cp16(uint32_t dst, const void* src) {
    asm volatile("cp.async.cg.shared.global [%0], [%1], 16;\n" :: "r"(dst), "l"(src) : "memory");
}
__device__ __forceinline__ void cp_commit() {
    asm volatile("cp.async.commit_group;\n" ::: "memory");
}
template <int N>
__device__ __forceinline__ void cp_wait() {
    asm volatile("cp.async.wait_group %0;\n" :: "n"(N) : "memory");
}
__device__ __forceinline__ void ldsm_x4(uint32_t addr, uint32_t& r0, uint32_t& r1, uint32_t& r2, uint32_t& r3) {
    asm volatile("ldmatrix.sync.aligned.m8n8.x4.shared.b16 {%0,%1,%2,%3}, [%4];\n"
                 : "=r"(r0), "=r"(r1), "=r"(r2), "=r"(r3) : "r"(addr));
}
__device__ __forceinline__ void ldsm_x2(uint32_t addr, uint32_t& r0, uint32_t& r1) {
    asm volatile("ldmatrix.sync.aligned.m8n8.x2.shared.b16 {%0,%1}, [%2];\n"
                 : "=r"(r0), "=r"(r1) : "r"(addr));
}
__device__ __forceinline__ void mma16816(float* c, uint32_t a0, uint32_t a1, uint32_t a2, uint32_t a3,
                                         uint32_t b0, uint32_t b1) {
    asm volatile("mma.sync.aligned.m16n8k16.row.col.f32.f16.f16.f32 "
                 "{%0,%1,%2,%3},{%4,%5,%6,%7},{%8,%9},{%0,%1,%2,%3};\n"
                 : "+f"(c[0]), "+f"(c[1]), "+f"(c[2]), "+f"(c[3])
                 : "r"(a0), "r"(a1), "r"(a2), "r"(a3), "r"(b0), "r"(b1));
}
__device__ __forceinline__ unsigned ld_acq(const unsigned* p) {
    unsigned v;
    asm volatile("ld.acquire.gpu.u32 %0, [%1];" : "=r"(v) : "l"(p) : "memory");
    return v;
}
__device__ __forceinline__ void pair_bar(int band) {
    asm volatile("bar.sync %0, 64;" :: "r"(band + 1) : "memory");
}

// ---------------- grid barrier (init/final only) ----------------
__device__ __forceinline__ void grid_barrier() {
    __syncthreads();
    if (threadIdx.x == 0) {
        unsigned my = *(volatile unsigned*)&g_bar_gen;
        __threadfence();
        unsigned a = atomicAdd(&g_bar_count, 1u);
        if (a == NBLK - 1) {
            *(volatile unsigned*)&g_bar_count = 0u;
            __threadfence();
            atomicAdd(&g_bar_gen, 1u);
        } else {
            while (*(volatile unsigned*)&g_bar_gen == my) { __nanosleep(40); }
        }
        __threadfence();
    }
    __syncthreads();
}

// ---------------- kernel 1: transpose/pad x to fp16 (+1 zero step) ----------------
__global__ void __launch_bounds__(256) xform_kernel(const float* __restrict__ x) {
    int t = blockIdx.x;
    const float* xs = x + (size_t)t * BATCH * DIM;
    __half* o = g_xT + (size_t)t * BATCH * XW;
    for (int i = threadIdx.x; i < BATCH * XW; i += 256) {
        int b = i >> 7, k = i & 127;
        float v = (t < T_STEPS && k < DIM) ? xs[b * DIM + k] : 0.0f;
        o[i] = __float2half_rn(v);
    }
}

// ---------------- kernel 2: persistent RNN, 16 warps/SM, pair-shared slabs ----------------
__global__ void __launch_bounds__(NTH, 1)
rnn_kernel(const float* __restrict__ W_ih, const float* __restrict__ b_ih,
           const float* __restrict__ W_hh, const float* __restrict__ b_hh,
           const float* __restrict__ W_out, const float* __restrict__ b_out,
           float* __restrict__ out)
{
    extern __shared__ char smem[];
    __half* sW    = (__half*)(smem + SMEM_W_OFF);
    float*  sBias = (float*)(smem + SMEM_BIAS_OFF);

    const int tid  = threadIdx.x;
    const int blk  = blockIdx.x;
    const int j0   = blk * JT;
    const int lane = tid & 31;
    const int warp = tid >> 5;       // 0..15
    const int band = warp & 7;       // row band: rows 16*band..+16
    const int colh = warp >> 3;      // column half: cols j0+8*colh..+8

    // ---- prologue: W slice fp16 (zero pads first) ----
    for (int i = tid; i < (JT * WPITCH_B) / 4; i += NTH)
        ((uint32_t*)sW)[i] = 0u;
    __syncthreads();
    for (int i = tid; i < JT * HID; i += NTH) {
        int n = i >> 10, k = i & 1023;
        sW[n * WPITCH_H + k] = __float2half_rn(W_hh[(j0 + n) * HID + k]);
    }
    for (int i = tid; i < JT * DIM; i += NTH) {
        int n = i / DIM, d = i % DIM;
        sW[n * WPITCH_H + HID + d] = __float2half_rn(W_ih[(j0 + n) * DIM + d]);
    }
    if (tid < JT) sBias[tid] = b_ih[j0 + tid] + b_hh[j0 + tid];

    // zero h buffer 0: 16384 uint4 over 32768 threads
    {
        int i = blk * NTH + tid;
        if (i < (BATCH * HID) / 8) {
            uint4 z = make_uint4(0u, 0u, 0u, 0u);
            ((uint4*)g_h[0])[i] = z;
        }
    }
    grid_barrier();

    // ---- per-warp geometry ----
    uint32_t smem_u = (uint32_t)__cvta_generic_to_shared(smem);
    const uint32_t aslot = smem_u + band * (NSLOT * AW_B);
    const uint32_t aoff = (lane & 15) * APITCH_B + ((lane >> 4) * 16);    // ldsm x4: 16 rows
    const uint32_t boff = smem_u + SMEM_W_OFF
        + (colh * 8 + (lane & 7)) * WPITCH_B + (((lane >> 3) & 1) * 16);  // ldsm x2: 8 cols

    const int er  = lane >> 2;
    const int ecc = (lane & 3) * 2;
    const int grow = 16 * band;           // band's batch-row base
    const int jc  = j0 + colh * 8 + ecc;  // this warp's output column base
    const int gp  = blk >> 3;             // producer group of this block
    const int rot = blk & 7;              // rotated start group
    unsigned* mycnt = &g_cnt[band * 32 + gp];
    const unsigned* pollbase = &g_cnt[band * 32];

    const float bia0 = sBias[colh * 8 + ecc], bib0 = sBias[colh * 8 + ecc + 1];

    // half-slab load: this warp loads rows [8*colh, 8*colh+8) of the band slab
    // 8 rows x 16 cc of 16B = 128 ops over 32 lanes = 4 iters
    const int lrow = (lane >> 4) + colh * 8;   // + i*2 per iter
    const int lcc  = lane & 15;

    #define LOAD_HALF(slotbase, srcptr, pitch) do {                                   \
        _Pragma("unroll")                                                             \
        for (int i_ = 0; i_ < 4; ++i_) {                                              \
            int r_ = lrow + i_ * 2;                                                   \
            cp16((slotbase) + r_ * APITCH_B + lcc * 16,                               \
                 (srcptr) + (r_) * (pitch) + lcc * 8);                                \
        }                                                                             \
    } while (0)

    // pre-loop: issue x_0 halves + empty group (so first wait<1> lands on x)
    {
        const __half* hx = g_xT + grow * XW;
        LOAD_HALF(aslot + SLOT_X * AW_B, hx, XW);
        cp_commit();
        cp_commit();   // empty group
    }

    // ---- time loop ----
    for (int t = 0; t < T_STEPS; ++t) {
        const __half* hrow = g_h[t % 3] + grow * HID;
        __half* hnxt = g_h[(t + 1) % 3];
        const unsigned tgt = 16u * (unsigned)t;

        float acc[8];
        #pragma unroll
        for (int i = 0; i < 8; ++i) acc[i] = 0.0f;

        unsigned mask = (t == 0) ? 0xFFu : 0u;
        #define ENSURE(gg) while (!((mask >> (gg)) & 1u)) {                         \
            unsigned v_ = (lane < 8) ? ld_acq(pollbase + lane) : 0u;                \
            mask |= __ballot_sync(0xFFFFFFFFu, (lane < 8) && (v_ >= tgt)) & 0xFFu;  \
        }

        // it0': x chunk — wait, pair-bar, compute (hides producer-tail latency)
        cp_wait<1>();
        pair_bar(band);
        {
            uint32_t ab = aslot + SLOT_X * AW_B + aoff;
            uint32_t bb = boff + HID * 2;
            #pragma unroll
            for (int s = 0; s < 8; ++s) {
                uint32_t a0, a1, a2, a3, b0, b1;
                ldsm_x2(bb + s * 32, b0, b1);
                ldsm_x4(ab + s * 32, a0, a1, a2, a3);
                mma16816(acc + (s & 1) * 4, a0, a1, a2, a3, b0, b1);
            }
        }

        // issue h chunks 1..3 (groups rot..rot+2) into slots 0..2
        #pragma unroll
        for (int c = 1; c <= 3; ++c) {
            const int g = (rot + c - 1) & 7;
            ENSURE(g);
            LOAD_HALF(aslot + ((c - 1) & 3) * AW_B, hrow + g * KC, HID);
            cp_commit();
        }

        // h iterations k = 1..8: wait, bar, compute chunk k, commit chunk k+3 (k<=5)
        #pragma unroll
        for (int k = 1; k <= 8; ++k) {
            if (k <= 4)      cp_wait<2>();
            else if (k <= 6) cp_wait<3>();
            else if (k == 7) cp_wait<2>();
            else             cp_wait<0>();
            pair_bar(band);

            const int g = (rot + k - 1) & 7;
            uint32_t ab = aslot + ((k - 1) & 3) * AW_B + aoff;
            uint32_t bb = boff + g * 256;
            #pragma unroll
            for (int s = 0; s < 8; ++s) {
                uint32_t a0, a1, a2, a3, b0, b1;
                ldsm_x2(bb + s * 32, b0, b1);
                ldsm_x4(ab + s * 32, a0, a1, a2, a3);
                mma16816(acc + (s & 1) * 4, a0, a1, a2, a3, b0, b1);
            }

            if (k <= 5) {
                const int cn = k + 3;                 // chunk to commit
                const int gn = (rot + cn - 1) & 7;
                ENSURE(gn);
                LOAD_HALF(aslot + ((cn - 1) & 3) * AW_B, hrow + gn * KC, HID);
                cp_commit();
            }
            if (k == 4) {
                const __half* hx = g_xT + (size_t)(t + 1) * (BATCH * XW) + grow * XW;
                LOAD_HALF(aslot + SLOT_X * AW_B, hx, XW);
                cp_commit();
            }
        }
        #undef ENSURE

        // ---- epilogue: merge split chains, bias + tanh + fp16 store ----
        {
            int row = grow + er;
            float h0 = tanhf(acc[0] + acc[4] + bia0);
            float h1 = tanhf(acc[1] + acc[5] + bib0);
            float h2 = tanhf(acc[2] + acc[6] + bia0);
            float h3 = tanhf(acc[3] + acc[7] + bib0);
            *reinterpret_cast<__half2*>(&hnxt[row * HID + jc])       = __floats2half2_rn(h0, h1);
            *reinterpret_cast<__half2*>(&hnxt[(row + 8) * HID + jc]) = __floats2half2_rn(h2, h3);
            if (t == T_STEPS - 1) {
                g_hlast[row * HID + jc]           = h0;
                g_hlast[row * HID + jc + 1]       = h1;
                g_hlast[(row + 8) * HID + jc]     = h2;
                g_hlast[(row + 8) * HID + jc + 1] = h3;
            }
        }

        // publish this warp's tile of step t
        __syncwarp();
        if (lane == 0) {
            asm volatile("red.release.gpu.global.add.u32 [%0], %1;"
                         :: "l"(mycnt), "r"(1u) : "memory");
        }
    }
    cp_wait<0>();

    // ---- drain, reset counters, readout ----
    grid_barrier();
    if (blk == 0) {
        if (tid < 256) g_cnt[tid] = 0u;
        for (int b = warp; b < BATCH; b += 16) {
            float a = 0.0f;
            #pragma unroll 4
            for (int j = lane; j < HID; j += 32)
                a += g_hlast[b * HID + j] * W_out[j];
            #pragma unroll
            for (int o = 16; o; o >>= 1) a += __shfl_xor_sync(0xFFFFFFFFu, a, o);
            if (lane == 0) out[b] = tanhf(a + b_out[0]);
        }
    }
}

// ---------------- launch ----------------
extern "C" void kernel_launch(void* const* d_in, const int* in_sizes, int n_in,
                              void* d_out, int out_size) {
    const float* x     = (const float*)d_in[0];
    const float* W_ih  = (const float*)d_in[1];
    const float* b_ih  = (const float*)d_in[2];
    const float* W_hh  = (const float*)d_in[3];
    const float* b_hh  = (const float*)d_in[4];
    const float* W_out = (const float*)d_in[5];
    const float* b_out = (const float*)d_in[6];

    cudaFuncSetAttribute(rnn_kernel, cudaFuncAttributeMaxDynamicSharedMemorySize, SMEM_TOTAL);

    xform_kernel<<<T_STEPS + 1, 256>>>(x);
    rnn_kernel<<<NBLK, NTH, SMEM_TOTAL>>>(W_ih, b_ih, W_hh, b_hh, W_out, b_out, (float*)d_out);
}

// round 9
// speedup vs baseline: 1.4684x; 1.4684x over previous
#include <cuda_runtime.h>
#include <cuda_fp16.h>
#include <cstdint>

#define T_STEPS 2048
#define BATCH   128
#define DIM     100
#define HID     1024
#define NBLK    128         // 8 row-groups x 16 col-CTAs
#define NTH     256         // 8 warps: 4 n-groups x 2 k-halves
#define CCOL    64          // columns per CTA
#define CH_H    2176        // halfs per chunk image (16 rows x 136 pitch)
#define CH_B    4352        // bytes per chunk
#define APITCH  272         // bytes per A row (128 halfs + 8 pad)
#define WPITCH_H 1160       // halfs per W row (1152 + 8 pad)
#define WPITCH_B 2320

// ---- smem layout (bytes) ----
#define SA_OFF    0                      // 8 h-chunk slots: 34816
#define SX_OFF    34816                  // 2 x slots: 8704
#define SW_OFF    43520                  // W slice: 64*2320 = 148480
#define SBIAS_OFF 192000                 // 256
#define SPART_OFF 192256                 // partials: 2*4*1024 = 8192
#define SMB_OFF   200448                 // 10 mbars * 8
#define SMEM_TOTAL 200704

// ---------------- device scratch ----------------
__device__ __align__(256) __half g_xT[(size_t)(T_STEPS + 1) * 8 * CH_H]; // [t][group][chunk-image]
__device__ __align__(256) __half g_h[2 * 8 * 8 * CH_H];                  // [buf][group][chunk][2176]
__device__ float  g_hlast[BATCH * HID];
__device__ unsigned g_cnt[8 * 16];       // [group][rank], +4 per step per CTA
__device__ unsigned g_bar_count;
__device__ unsigned g_bar_gen;

// ---------------- PTX helpers ----------------
__device__ __forceinline__ void ldsm_x4(uint32_t addr, uint32_t& r0, uint32_t& r1, uint32_t& r2, uint32_t& r3) {
    asm volatile("ldmatrix.sync.aligned.m8n8.x4.shared.b16 {%0,%1,%2,%3}, [%4];\n"
                 : "=r"(r0), "=r"(r1), "=r"(r2), "=r"(r3) : "r"(addr));
}
__device__ __forceinline__ void mma16816(float* c, uint32_t a0, uint32_t a1, uint32_t a2, uint32_t a3,
                                         uint32_t b0, uint32_t b1) {
    asm volatile("mma.sync.aligned.m16n8k16.row.col.f32.f16.f16.f32 "
                 "{%0,%1,%2,%3},{%4,%5,%6,%7},{%8,%9},{%0,%1,%2,%3};\n"
                 : "+f"(c[0]), "+f"(c[1]), "+f"(c[2]), "+f"(c[3])
                 : "r"(a0), "r"(a1), "r"(a2), "r"(a3), "r"(b0), "r"(b1));
}
__device__ __forceinline__ unsigned ld_acq(const unsigned* p) {
    unsigned v;
    asm volatile("ld.acquire.gpu.u32 %0, [%1];" : "=r"(v) : "l"(p) : "memory");
    return v;
}
__device__ __forceinline__ void mbar_init(uint32_t mbar, uint32_t cnt) {
    asm volatile("mbarrier.init.shared.b64 [%0], %1;" :: "r"(mbar), "r"(cnt) : "memory");
}
__device__ __forceinline__ void mbar_expect_tx(uint32_t mbar, uint32_t bytes) {
    asm volatile("mbarrier.arrive.expect_tx.shared.b64 _, [%0], %1;" :: "r"(mbar), "r"(bytes) : "memory");
}
__device__ __forceinline__ void bulk_g2s(uint32_t dst, const void* src, uint32_t bytes, uint32_t mbar) {
    asm volatile("cp.async.bulk.shared::cluster.global.mbarrier::complete_tx::bytes [%0], [%1], %2, [%3];"
                 :: "r"(dst), "l"(src), "r"(bytes), "r"(mbar) : "memory");
}
__device__ __forceinline__ void mbar_wait(uint32_t mbar, uint32_t parity) {
    uint32_t done;
    do {
        asm volatile("{\n\t.reg .pred p;\n\t"
                     "mbarrier.try_wait.parity.acquire.cta.shared::cta.b64 p, [%1], %2, 0x989680;\n\t"
                     "selp.b32 %0, 1, 0, p;\n\t}"
                     : "=r"(done) : "r"(mbar), "r"(parity) : "memory");
    } while (!done);
}

// ---------------- grid barrier (init/final only) ----------------
__device__ __forceinline__ void grid_barrier() {
    __syncthreads();
    if (threadIdx.x == 0) {
        unsigned my = *(volatile unsigned*)&g_bar_gen;
        __threadfence();
        unsigned a = atomicAdd(&g_bar_count, 1u);
        if (a == NBLK - 1) {
            *(volatile unsigned*)&g_bar_count = 0u;
            __threadfence();
            atomicAdd(&g_bar_gen, 1u);
        } else {
            while (*(volatile unsigned*)&g_bar_gen == my) { __nanosleep(40); }
        }
        __threadfence();
    }
    __syncthreads();
}

// ---------------- kernel 1: x -> [t][group][16 rows x 136 pitch] fp16 ----------------
__global__ void __launch_bounds__(256) xform_kernel(const float* __restrict__ x) {
    int t = blockIdx.x;
    __half* o = g_xT + (size_t)t * 8 * CH_H;
    for (int i = threadIdx.x; i < 8 * CH_H; i += 256) {
        int g = i / CH_H, idx = i % CH_H;
        int row = idx / 136, k = idx % 136;
        float v = 0.0f;
        if (t < T_STEPS && k < DIM)
            v = x[((size_t)t * BATCH + (16 * g + row)) * DIM + k];
        o[i] = __float2half_rn(v);
    }
}

// ---------------- kernel 2: persistent RNN, batch-split tiling ----------------
__global__ void __launch_bounds__(NTH, 1)
rnn_kernel(const float* __restrict__ W_ih, const float* __restrict__ b_ih,
           const float* __restrict__ W_hh, const float* __restrict__ b_hh,
           const float* __restrict__ W_out, const float* __restrict__ b_out,
           float* __restrict__ out)
{
    extern __shared__ char smem[];
    __half* sW    = (__half*)(smem + SW_OFF);
    float*  sBias = (float*)(smem + SBIAS_OFF);
    float*  sPart = (float*)(smem + SPART_OFF);

    const int tid  = threadIdx.x;
    const int blk  = blockIdx.x;
    const int g    = blk >> 4;       // row group: batch rows [16g, 16g+16)
    const int r    = blk & 15;       // rank: cols [64r, 64r+64)
    const int lane = tid & 31;
    const int warp = tid >> 5;       // 8 warps
    const int nw   = warp & 3;       // n-group: local cols [16nw, 16nw+16)
    const int ks   = warp >> 2;      // k-half within each 128-k chunk

    uint32_t smem_u = (uint32_t)__cvta_generic_to_shared(smem);
    const uint32_t MB = smem_u + SMB_OFF;     // h mbars 0..7, x mbars 8,9

    // ---- prologue: W slice (zero pads then fill) ----
    for (int i = tid; i < (CCOL * WPITCH_B) / 4; i += NTH)
        ((uint32_t*)sW)[i] = 0u;
    __syncthreads();
    for (int i = tid; i < CCOL * HID; i += NTH) {
        int n = i >> 10, k = i & 1023;
        sW[n * WPITCH_H + k] = __float2half_rn(W_hh[(64 * r + n) * HID + k]);
    }
    for (int i = tid; i < CCOL * DIM; i += NTH) {
        int n = i / DIM, d = i % DIM;
        sW[n * WPITCH_H + HID + d] = __float2half_rn(W_ih[(64 * r + n) * DIM + d]);
    }
    if (tid < CCOL) sBias[tid] = b_ih[64 * r + tid] + b_hh[64 * r + tid];

    // zero h buf 0 (incl pads): 278528 B = 17408 uint4 over 32768 threads
    {
        int i = blk * NTH + tid;
        if (i < 17408) ((uint4*)g_h)[i] = make_uint4(0u, 0u, 0u, 0u);
    }
    if (tid == 0) {
        #pragma unroll
        for (int m = 0; m < 10; ++m) mbar_init(MB + m * 8, 1);
    }
    grid_barrier();

    // prologue bulk issues: x0 -> xbuf0, x1 -> xbuf1, h(0) chunks
    if (tid == 0) {
        mbar_expect_tx(MB + 8 * 8, CH_B);
        bulk_g2s(smem_u + SX_OFF, &g_xT[(size_t)0 * 8 * CH_H + g * CH_H], CH_B, MB + 8 * 8);
        mbar_expect_tx(MB + 9 * 8, CH_B);
        bulk_g2s(smem_u + SX_OFF + CH_B, &g_xT[(size_t)1 * 8 * CH_H + g * CH_H], CH_B, MB + 9 * 8);
        #pragma unroll
        for (int c = 0; c < 8; ++c) {
            mbar_expect_tx(MB + c * 8, CH_B);
            bulk_g2s(smem_u + SA_OFF + c * CH_B, &g_h[(size_t)(0 * 8 + g) * 8 * CH_H + c * CH_H], CH_B, MB + c * 8);
        }
    }

    // ---- per-warp addressing ----
    const uint32_t aoff = (lane & 15) * APITCH + ((lane >> 4) * 16) + ks * 128;
    const uint32_t boff = smem_u + SW_OFF
        + (16 * nw + (lane & 7) + ((lane & 16) >> 1)) * WPITCH_B
        + (((lane >> 3) & 1) * 16) + ks * 128;

    const int er  = lane >> 2;
    const int ecc = 2 * (lane & 3);
    unsigned* mycnt = &g_cnt[g * 16 + r];
    const unsigned* pollbase = &g_cnt[g * 16];

    // ---- time loop ----
    for (int t = 0; t < T_STEPS; ++t) {
        float acc[8];
        #pragma unroll
        for (int i = 0; i < 8; ++i) acc[i] = 0.0f;

        // x chunk (prefetched one step ahead)
        mbar_wait(MB + (8 + (t & 1)) * 8, (unsigned)((t >> 1) & 1));
        {
            uint32_t ab = smem_u + SX_OFF + (t & 1) * CH_B + aoff;
            uint32_t bb = boff + 2048;
            #pragma unroll
            for (int s = 0; s < 4; ++s) {
                uint32_t a0, a1, a2, a3, b0, b1, b2, b3;
                ldsm_x4(bb + s * 32, b0, b1, b2, b3);
                ldsm_x4(ab + s * 32, a0, a1, a2, a3);
                mma16816(acc + 0, a0, a1, a2, a3, b0, b1);
                mma16816(acc + 4, a0, a1, a2, a3, b2, b3);
            }
        }

        // h chunks 0..7 gated by mbars
        #pragma unroll
        for (int c = 0; c < 8; ++c) {
            mbar_wait(MB + c * 8, (unsigned)(t & 1));
            uint32_t ab = smem_u + SA_OFF + c * CH_B + aoff;
            uint32_t bb = boff + c * 256;
            #pragma unroll
            for (int s = 0; s < 4; ++s) {
                uint32_t a0, a1, a2, a3, b0, b1, b2, b3;
                ldsm_x4(bb + s * 32, b0, b1, b2, b3);
                ldsm_x4(ab + s * 32, a0, a1, a2, a3);
                mma16816(acc + 0, a0, a1, a2, a3, b0, b1);
                mma16816(acc + 4, a0, a1, a2, a3, b2, b3);
            }
        }

        if (warp >= 4) {
            // store partials, arrive (non-blocking), race ahead
            float* p = sPart + (t & 1) * 1024 + nw * 256 + lane * 8;
            *reinterpret_cast<float4*>(p)     = make_float4(acc[0], acc[1], acc[2], acc[3]);
            *reinterpret_cast<float4*>(p + 4) = make_float4(acc[4], acc[5], acc[6], acc[7]);
            __threadfence_block();
            asm volatile("bar.arrive 1, 256;" ::: "memory");
        } else {
            asm volatile("bar.sync 1, 256;" ::: "memory");
            const float* p = sPart + (t & 1) * 1024 + nw * 256 + lane * 8;
            float4 q0 = *reinterpret_cast<const float4*>(p);
            float4 q1 = *reinterpret_cast<const float4*>(p + 4);

            const int jl = 16 * nw + ecc;             // local col
            const float bi0 = sBias[jl], bi1 = sBias[jl + 1];
            const float bi4 = sBias[jl + 8], bi5 = sBias[jl + 9];
            float h0 = tanhf(acc[0] + q0.x + bi0);
            float h1 = tanhf(acc[1] + q0.y + bi1);
            float h2 = tanhf(acc[2] + q0.z + bi0);
            float h3 = tanhf(acc[3] + q0.w + bi1);
            float h4 = tanhf(acc[4] + q1.x + bi4);
            float h5 = tanhf(acc[5] + q1.y + bi5);
            float h6 = tanhf(acc[6] + q1.z + bi4);
            float h7 = tanhf(acc[7] + q1.w + bi5);

            const int jc = 64 * r + jl;               // global col
            const int ch = jc >> 7, cc = jc & 127;
            __half* hb = g_h + (size_t)(((t + 1) & 1) * 8 + g) * 8 * CH_H + ch * CH_H;
            *reinterpret_cast<__half2*>(&hb[er * 136 + cc])           = __floats2half2_rn(h0, h1);
            *reinterpret_cast<__half2*>(&hb[(er + 8) * 136 + cc])     = __floats2half2_rn(h2, h3);
            *reinterpret_cast<__half2*>(&hb[er * 136 + cc + 8])       = __floats2half2_rn(h4, h5);
            *reinterpret_cast<__half2*>(&hb[(er + 8) * 136 + cc + 8]) = __floats2half2_rn(h6, h7);
            if (t == T_STEPS - 1) {
                int gr0 = 16 * g + er, gr1 = gr0 + 8;
                g_hlast[gr0 * HID + jc]     = h0;
                g_hlast[gr0 * HID + jc + 1] = h1;
                g_hlast[gr1 * HID + jc]     = h2;
                g_hlast[gr1 * HID + jc + 1] = h3;
                g_hlast[gr0 * HID + jc + 8] = h4;
                g_hlast[gr0 * HID + jc + 9] = h5;
                g_hlast[gr1 * HID + jc + 8] = h6;
                g_hlast[gr1 * HID + jc + 9] = h7;
            }
            __syncwarp();
            if (lane == 0)
                asm volatile("red.release.gpu.global.add.u32 [%0], %1;"
                             :: "l"(mycnt), "r"(1u) : "memory");

            // warp 0: poll + issue next step's bulks
            if (warp == 0 && t + 1 < T_STEPS) {
                const unsigned tgt = 4u * (unsigned)(t + 1);
                unsigned v;
                do {
                    v = ld_acq(pollbase + (lane & 15));
                } while (!__all_sync(0xFFFFFFFFu, v >= tgt));
                if (lane == 0) {
                    const int nb = (t + 1) & 1;
                    #pragma unroll
                    for (int c = 0; c < 8; ++c) {
                        mbar_expect_tx(MB + c * 8, CH_B);
                        bulk_g2s(smem_u + SA_OFF + c * CH_B,
                                 &g_h[(size_t)(nb * 8 + g) * 8 * CH_H + c * CH_H], CH_B, MB + c * 8);
                    }
                    mbar_expect_tx(MB + (8 + (t & 1)) * 8, CH_B);
                    bulk_g2s(smem_u + SX_OFF + (t & 1) * CH_B,
                             &g_xT[(size_t)(t + 2) * 8 * CH_H + g * CH_H], CH_B, MB + (8 + (t & 1)) * 8);
                }
            }
        }
    }

    // ---- drain, reset counters, readout ----
    grid_barrier();
    if (blk == 0) {
        if (tid < 128) g_cnt[tid] = 0u;
        for (int b = warp; b < BATCH; b += 8) {
            float a = 0.0f;
            #pragma unroll 4
            for (int j = lane; j < HID; j += 32)
                a += g_hlast[b * HID + j] * W_out[j];
            #pragma unroll
            for (int o = 16; o; o >>= 1) a += __shfl_xor_sync(0xFFFFFFFFu, a, o);
            if (lane == 0) out[b] = tanhf(a + b_out[0]);
        }
    }
}

// ---------------- launch ----------------
extern "C" void kernel_launch(void* const* d_in, const int* in_sizes, int n_in,
                              void* d_out, int out_size) {
    const float* x     = (const float*)d_in[0];
    const float* W_ih  = (const float*)d_in[1];
    const float* b_ih  = (const float*)d_in[2];
    const float* W_hh  = (const float*)d_in[3];
    const float* b_hh  = (const float*)d_in[4];
    const float* W_out = (const float*)d_in[5];
    const float* b_out = (const float*)d_in[6];

    cudaFuncSetAttribute(rnn_kernel, cudaFuncAttributeMaxDynamicSharedMemorySize, SMEM_TOTAL);

    xform_kernel<<<T_STEPS + 1, 256>>>(x);
    rnn_kernel<<<NBLK, NTH, SMEM_TOTAL>>>(W_ih, b_ih, W_hh, b_hh, W_out, b_out, (float*)d_out);
}

// round 10
// speedup vs baseline: 2.0276x; 1.3808x over previous
#include <cuda_runtime.h>
#include <cuda_fp16.h>
#include <cstdint>

#define T_STEPS 2048
#define BATCH   128
#define DIM     100
#define HID     1024
#define NBLK    128         // 8 row-groups x 16 col-CTAs
#define NTH     256         // 8 warps: 4 n-groups x 2 k-halves
#define CCOL    64          // columns per CTA
#define CH_H    2176        // halfs per chunk image (16 rows x 136 pitch)
#define CH_B    4352        // bytes per chunk
#define APITCH  272         // bytes per A row (128 halfs + 8 pad)
#define WPITCH_H 1160       // halfs per W row (1152 + 8 pad)
#define WPITCH_B 2320

// ---- smem layout (bytes) ----
#define SA_OFF    0                      // 8 h-chunk slots: 34816
#define SX_OFF    34816                  // 2 x slots: 8704
#define SW_OFF    43520                  // W slice: 64*2320 = 148480
#define SBIAS_OFF 192000                 // 256
#define SPART_OFF 192256                 // partials: 2*4*1024 = 8192
#define SMB_OFF   200448                 // 10 mbars * 8
#define SMEM_TOTAL 200704

// ---------------- device scratch ----------------
__device__ __align__(256) __half g_xT[(size_t)(T_STEPS + 1) * 8 * CH_H]; // [t][group][chunk-image]
__device__ __align__(256) __half g_h[2 * 8 * 8 * CH_H];                  // [buf][group][chunk][2176]
__device__ float  g_hlast[BATCH * HID];
__device__ unsigned g_cnt[8 * 16];       // [group][rank], +4 per step per CTA
__device__ unsigned g_bar_count;
__device__ unsigned g_bar_gen;

// ---------------- PTX helpers ----------------
__device__ __forceinline__ void ldsm_x4(uint32_t addr, uint32_t& r0, uint32_t& r1, uint32_t& r2, uint32_t& r3) {
    asm volatile("ldmatrix.sync.aligned.m8n8.x4.shared.b16 {%0,%1,%2,%3}, [%4];\n"
                 : "=r"(r0), "=r"(r1), "=r"(r2), "=r"(r3) : "r"(addr));
}
__device__ __forceinline__ void mma16816(float* c, uint32_t a0, uint32_t a1, uint32_t a2, uint32_t a3,
                                         uint32_t b0, uint32_t b1) {
    asm volatile("mma.sync.aligned.m16n8k16.row.col.f32.f16.f16.f32 "
                 "{%0,%1,%2,%3},{%4,%5,%6,%7},{%8,%9},{%0,%1,%2,%3};\n"
                 : "+f"(c[0]), "+f"(c[1]), "+f"(c[2]), "+f"(c[3])
                 : "r"(a0), "r"(a1), "r"(a2), "r"(a3), "r"(b0), "r"(b1));
}
__device__ __forceinline__ unsigned ld_acq(const unsigned* p) {
    unsigned v;
    asm volatile("ld.acquire.gpu.u32 %0, [%1];" : "=r"(v) : "l"(p) : "memory");
    return v;
}
__device__ __forceinline__ void mbar_init(uint32_t mbar, uint32_t cnt) {
    asm volatile("mbarrier.init.shared.b64 [%0], %1;" :: "r"(mbar), "r"(cnt) : "memory");
}
__device__ __forceinline__ void mbar_expect_tx(uint32_t mbar, uint32_t bytes) {
    asm volatile("mbarrier.arrive.expect_tx.shared.b64 _, [%0], %1;" :: "r"(mbar), "r"(bytes) : "memory");
}
__device__ __forceinline__ void bulk_g2s(uint32_t dst, const void* src, uint32_t bytes, uint32_t mbar) {
    asm volatile("cp.async.bulk.shared::cluster.global.mbarrier::complete_tx::bytes [%0], [%1], %2, [%3];"
                 :: "r"(dst), "l"(src), "r"(bytes), "r"(mbar) : "memory");
}
__device__ __forceinline__ void mbar_wait(uint32_t mbar, uint32_t parity) {
    uint32_t done;
    do {
        asm volatile("{\n\t.reg .pred p;\n\t"
                     "mbarrier.try_wait.parity.acquire.cta.shared::cta.b64 p, [%1], %2, 0x989680;\n\t"
                     "selp.b32 %0, 1, 0, p;\n\t}"
                     : "=r"(done) : "r"(mbar), "r"(parity) : "memory");
    } while (!done);
}

// ---------------- grid barrier (init/final only) ----------------
__device__ __forceinline__ void grid_barrier() {
    __syncthreads();
    if (threadIdx.x == 0) {
        unsigned my = *(volatile unsigned*)&g_bar_gen;
        __threadfence();
        unsigned a = atomicAdd(&g_bar_count, 1u);
        if (a == NBLK - 1) {
            *(volatile unsigned*)&g_bar_count = 0u;
            __threadfence();
            atomicAdd(&g_bar_gen, 1u);
        } else {
            while (*(volatile unsigned*)&g_bar_gen == my) { __nanosleep(40); }
        }
        __threadfence();
    }
    __syncthreads();
}

// ---------------- kernel 1: x -> [t][group][16 rows x 136 pitch] fp16 ----------------
__global__ void __launch_bounds__(256) xform_kernel(const float* __restrict__ x) {
    int t = blockIdx.x;
    __half* o = g_xT + (size_t)t * 8 * CH_H;
    for (int i = threadIdx.x; i < 8 * CH_H; i += 256) {
        int g = i / CH_H, idx = i % CH_H;
        int row = idx / 136, k = idx % 136;
        float v = 0.0f;
        if (t < T_STEPS && k < DIM)
            v = x[((size_t)t * BATCH + (16 * g + row)) * DIM + k];
        o[i] = __float2half_rn(v);
    }
}

// ---------------- kernel 2: persistent RNN, batch-split, per-chunk gating ----------------
__global__ void __launch_bounds__(NTH, 1)
rnn_kernel(const float* __restrict__ W_ih, const float* __restrict__ b_ih,
           const float* __restrict__ W_hh, const float* __restrict__ b_hh,
           const float* __restrict__ W_out, const float* __restrict__ b_out,
           float* __restrict__ out)
{
    extern __shared__ char smem[];
    __half* sW    = (__half*)(smem + SW_OFF);
    float*  sBias = (float*)(smem + SBIAS_OFF);
    float*  sPart = (float*)(smem + SPART_OFF);

    const int tid  = threadIdx.x;
    const int blk  = blockIdx.x;
    const int g    = blk >> 4;       // row group: batch rows [16g, 16g+16)
    const int r    = blk & 15;       // rank: cols [64r, 64r+64)
    const int rot  = r & 7;          // rotated chunk start
    const int lane = tid & 31;
    const int warp = tid >> 5;       // 8 warps
    const int nw   = warp & 3;       // n-group: local cols [16nw, 16nw+16)
    const int ks   = warp >> 2;      // k-half within each 128-k chunk

    uint32_t smem_u = (uint32_t)__cvta_generic_to_shared(smem);
    const uint32_t MB = smem_u + SMB_OFF;     // h mbars 0..7 (by slot), x mbars 8,9

    // ---- prologue: W slice (zero pads then fill) ----
    for (int i = tid; i < (CCOL * WPITCH_B) / 4; i += NTH)
        ((uint32_t*)sW)[i] = 0u;
    __syncthreads();
    for (int i = tid; i < CCOL * HID; i += NTH) {
        int n = i >> 10, k = i & 1023;
        sW[n * WPITCH_H + k] = __float2half_rn(W_hh[(64 * r + n) * HID + k]);
    }
    for (int i = tid; i < CCOL * DIM; i += NTH) {
        int n = i / DIM, d = i % DIM;
        sW[n * WPITCH_H + HID + d] = __float2half_rn(W_ih[(64 * r + n) * DIM + d]);
    }
    if (tid < CCOL) sBias[tid] = b_ih[64 * r + tid] + b_hh[64 * r + tid];

    // zero h buf 0 (incl pads): 278528 B = 17408 uint4 over 32768 threads
    {
        int i = blk * NTH + tid;
        if (i < 17408) ((uint4*)g_h)[i] = make_uint4(0u, 0u, 0u, 0u);
    }
    if (tid == 0) {
        #pragma unroll
        for (int m = 0; m < 10; ++m) mbar_init(MB + m * 8, 1);
    }
    grid_barrier();

    // prologue bulk issues: x0, x1, h(0) chunks in rotated order (slot j <- chunk (rot+j)&7)
    if (tid == 0) {
        mbar_expect_tx(MB + 8 * 8, CH_B);
        bulk_g2s(smem_u + SX_OFF, &g_xT[(size_t)0 * 8 * CH_H + g * CH_H], CH_B, MB + 8 * 8);
        mbar_expect_tx(MB + 9 * 8, CH_B);
        bulk_g2s(smem_u + SX_OFF + CH_B, &g_xT[(size_t)1 * 8 * CH_H + g * CH_H], CH_B, MB + 9 * 8);
        #pragma unroll
        for (int j = 0; j < 8; ++j) {
            const int cj = (rot + j) & 7;
            mbar_expect_tx(MB + j * 8, CH_B);
            bulk_g2s(smem_u + SA_OFF + j * CH_B, &g_h[(size_t)(0 * 8 + g) * 8 * CH_H + cj * CH_H], CH_B, MB + j * 8);
        }
    }

    // ---- per-warp addressing ----
    const uint32_t aoff = (lane & 15) * APITCH + ((lane >> 4) * 16) + ks * 128;
    const uint32_t boff = smem_u + SW_OFF
        + (16 * nw + (lane & 7) + ((lane & 16) >> 1)) * WPITCH_B
        + (((lane >> 3) & 1) * 16) + ks * 128;

    const int er  = lane >> 2;
    const int ecc = 2 * (lane & 3);
    unsigned* mycnt = &g_cnt[g * 16 + r];
    const unsigned* pollbase = &g_cnt[g * 16];

    // ---- time loop ----
    for (int t = 0; t < T_STEPS; ++t) {
        float acc[8];
        #pragma unroll
        for (int i = 0; i < 8; ++i) acc[i] = 0.0f;

        // x chunk (prefetched one step ahead)
        mbar_wait(MB + (8 + (t & 1)) * 8, (unsigned)((t >> 1) & 1));
        {
            uint32_t ab = smem_u + SX_OFF + (t & 1) * CH_B + aoff;
            uint32_t bb = boff + 2048;
            #pragma unroll
            for (int s = 0; s < 4; ++s) {
                uint32_t a0, a1, a2, a3, b0, b1, b2, b3;
                ldsm_x4(bb + s * 32, b0, b1, b2, b3);
                ldsm_x4(ab + s * 32, a0, a1, a2, a3);
                mma16816(acc + 0, a0, a1, a2, a3, b0, b1);
                mma16816(acc + 4, a0, a1, a2, a3, b2, b3);
            }
        }

        // h chunks in rotated order, gated by slot mbars
        #pragma unroll
        for (int j = 0; j < 8; ++j) {
            const int cj = (rot + j) & 7;
            mbar_wait(MB + j * 8, (unsigned)(t & 1));
            uint32_t ab = smem_u + SA_OFF + j * CH_B + aoff;
            uint32_t bb = boff + cj * 256;
            #pragma unroll
            for (int s = 0; s < 4; ++s) {
                uint32_t a0, a1, a2, a3, b0, b1, b2, b3;
                ldsm_x4(bb + s * 32, b0, b1, b2, b3);
                ldsm_x4(ab + s * 32, a0, a1, a2, a3);
                mma16816(acc + 0, a0, a1, a2, a3, b0, b1);
                mma16816(acc + 4, a0, a1, a2, a3, b2, b3);
            }
        }

        if (warp >= 4) {
            // store partials, arrive (non-blocking), race ahead
            float* p = sPart + (t & 1) * 1024 + nw * 256 + lane * 8;
            *reinterpret_cast<float4*>(p)     = make_float4(acc[0], acc[1], acc[2], acc[3]);
            *reinterpret_cast<float4*>(p + 4) = make_float4(acc[4], acc[5], acc[6], acc[7]);
            __threadfence_block();
            asm volatile("bar.arrive 1, 256;" ::: "memory");
        } else {
            asm volatile("bar.sync 1, 256;" ::: "memory");
            const float* p = sPart + (t & 1) * 1024 + nw * 256 + lane * 8;
            float4 q0 = *reinterpret_cast<const float4*>(p);
            float4 q1 = *reinterpret_cast<const float4*>(p + 4);

            const int jl = 16 * nw + ecc;             // local col
            const float bi0 = sBias[jl], bi1 = sBias[jl + 1];
            const float bi4 = sBias[jl + 8], bi5 = sBias[jl + 9];
            float h0 = tanhf(acc[0] + q0.x + bi0);
            float h1 = tanhf(acc[1] + q0.y + bi1);
            float h2 = tanhf(acc[2] + q0.z + bi0);
            float h3 = tanhf(acc[3] + q0.w + bi1);
            float h4 = tanhf(acc[4] + q1.x + bi4);
            float h5 = tanhf(acc[5] + q1.y + bi5);
            float h6 = tanhf(acc[6] + q1.z + bi4);
            float h7 = tanhf(acc[7] + q1.w + bi5);

            const int jc = 64 * r + jl;               // global col
            const int ch = jc >> 7, cc = jc & 127;
            __half* hb = g_h + (size_t)(((t + 1) & 1) * 8 + g) * 8 * CH_H + ch * CH_H;
            *reinterpret_cast<__half2*>(&hb[er * 136 + cc])           = __floats2half2_rn(h0, h1);
            *reinterpret_cast<__half2*>(&hb[(er + 8) * 136 + cc])     = __floats2half2_rn(h2, h3);
            *reinterpret_cast<__half2*>(&hb[er * 136 + cc + 8])       = __floats2half2_rn(h4, h5);
            *reinterpret_cast<__half2*>(&hb[(er + 8) * 136 + cc + 8]) = __floats2half2_rn(h6, h7);
            if (t == T_STEPS - 1) {
                int gr0 = 16 * g + er, gr1 = gr0 + 8;
                g_hlast[gr0 * HID + jc]     = h0;
                g_hlast[gr0 * HID + jc + 1] = h1;
                g_hlast[gr1 * HID + jc]     = h2;
                g_hlast[gr1 * HID + jc + 1] = h3;
                g_hlast[gr0 * HID + jc + 8] = h4;
                g_hlast[gr0 * HID + jc + 9] = h5;
                g_hlast[gr1 * HID + jc + 8] = h6;
                g_hlast[gr1 * HID + jc + 9] = h7;
            }
            __syncwarp();
            if (lane == 0)
                asm volatile("red.release.gpu.global.add.u32 [%0], %1;"
                             :: "l"(mycnt), "r"(1u) : "memory");

            // warp 0: per-chunk gated issue of next step's bulks
            if (warp == 0 && t + 1 < T_STEPS) {
                const unsigned tgt = 4u * (unsigned)(t + 1);
                const int nb = (t + 1) & 1;
                // x bulk first (no dependency)
                if (lane == 0) {
                    mbar_expect_tx(MB + (8 + (t & 1)) * 8, CH_B);
                    bulk_g2s(smem_u + SX_OFF + (t & 1) * CH_B,
                             &g_xT[(size_t)(t + 2) * 8 * CH_H + g * CH_H], CH_B, MB + (8 + (t & 1)) * 8);
                }
                unsigned pmask = 0u;   // bit c: chunk c's producer pair (ranks 2c,2c+1) ready
                #pragma unroll
                for (int j = 0; j < 8; ++j) {
                    const int cj = (rot + j) & 7;
                    while (!((pmask >> cj) & 1u)) {
                        unsigned v = (lane < 16) ? ld_acq(pollbase + lane) : tgt;
                        unsigned b = __ballot_sync(0xFFFFFFFFu, v >= tgt);
                        unsigned pr = b & (b >> 1);     // bit 2c set iff both ranks ready
                        unsigned m = 0u;
                        #pragma unroll
                        for (int p = 0; p < 8; ++p) m |= ((pr >> (2 * p)) & 1u) << p;
                        pmask |= m;
                    }
                    if (lane == 0) {
                        mbar_expect_tx(MB + j * 8, CH_B);
                        bulk_g2s(smem_u + SA_OFF + j * CH_B,
                                 &g_h[(size_t)(nb * 8 + g) * 8 * CH_H + cj * CH_H], CH_B, MB + j * 8);
                    }
                }
            }
        }
    }

    // ---- drain, reset counters, readout ----
    grid_barrier();
    if (blk == 0) {
        if (tid < 128) g_cnt[tid] = 0u;
        for (int b = warp; b < BATCH; b += 8) {
            float a = 0.0f;
            #pragma unroll 4
            for (int j = lane; j < HID; j += 32)
                a += g_hlast[b * HID + j] * W_out[j];
            #pragma unroll
            for (int o = 16; o; o >>= 1) a += __shfl_xor_sync(0xFFFFFFFFu, a, o);
            if (lane == 0) out[b] = tanhf(a + b_out[0]);
        }
    }
}

// ---------------- launch ----------------
extern "C" void kernel_launch(void* const* d_in, const int* in_sizes, int n_in,
                              void* d_out, int out_size) {
    const float* x     = (const float*)d_in[0];
    const float* W_ih  = (const float*)d_in[1];
    const float* b_ih  = (const float*)d_in[2];
    const float* W_hh  = (const float*)d_in[3];
    const float* b_hh  = (const float*)d_in[4];
    const float* W_out = (const float*)d_in[5];
    const float* b_out = (const float*)d_in[6];

    cudaFuncSetAttribute(rnn_kernel, cudaFuncAttributeMaxDynamicSharedMemorySize, SMEM_TOTAL);

    xform_kernel<<<T_STEPS + 1, 256>>>(x);
    rnn_kernel<<<NBLK, NTH, SMEM_TOTAL>>>(W_ih, b_ih, W_hh, b_hh, W_out, b_out, (float*)d_out);
}